// round 14
// baseline (speedup 1.0000x reference)
#include <cuda_runtime.h>
#include <cuda_fp16.h>
#include <cuda_bf16.h>
#include <cstdint>

#define N_NODES 10000
#define E_EDGES 640000
#define IN_CH   512
#define OUT_CH  256

// ---------------- device-global scratch (no allocations allowed) ----------------
__device__ int    g_deg[N_NODES];
__device__ int    g_rowptr[N_NODES + 1];
__device__ int    g_cursor[N_NODES];
__device__ float  g_dinv[N_NODES];
__device__ int    g_col[E_EDGES];
__device__ float  g_bufB[N_NODES * OUT_CH];
// hop-1 gather mirror: fp16, pre-scaled by dinv[row]
__device__ __half g_m0[N_NODES * OUT_CH];
// hop-2/3 gather mirrors: int8 + per-row fp32 scale (value*dinv = q*scale)
__device__ unsigned g_q1[N_NODES * OUT_CH / 4];
__device__ unsigned g_q2[N_NODES * OUT_CH / 4];
__device__ float    g_s1[N_NODES];
__device__ float    g_s2[N_NODES];
// bf16 hi/lo splits for the tensor-core GEMM
__device__ __nv_bfloat16 g_xh[N_NODES * IN_CH];
__device__ __nv_bfloat16 g_xl[N_NODES * IN_CH];
__device__ __nv_bfloat16 g_wh[OUT_CH * IN_CH];
__device__ __nv_bfloat16 g_wl[OUT_CH * IN_CH];

__device__ __forceinline__ uint32_t smem_u32(const void* p) {
    uint32_t a;
    asm("{ .reg .u64 t; cvta.to.shared.u64 t, %1; cvt.u32.u64 %0, t; }" : "=r"(a) : "l"(p));
    return a;
}

#define LDSM_X4(r0, r1, r2, r3, addr) \
    asm volatile("ldmatrix.sync.aligned.m8n8.x4.shared.b16 {%0,%1,%2,%3}, [%4];" \
                 : "=r"(r0), "=r"(r1), "=r"(r2), "=r"(r3) : "r"(addr))

#define MMA_BF16(d, a, b0, b1) \
    asm volatile( \
        "mma.sync.aligned.m16n8k16.row.col.f32.bf16.bf16.f32 " \
        "{%0,%1,%2,%3}, {%4,%5,%6,%7}, {%8,%9}, {%0,%1,%2,%3};" \
        : "+f"((d)[0]), "+f"((d)[1]), "+f"((d)[2]), "+f"((d)[3]) \
        : "r"((a)[0]), "r"((a)[1]), "r"((a)[2]), "r"((a)[3]), "r"(b0), "r"(b1))

// 16B async copy; src_sz = 16 (copy) or 0 (zero-fill)
#define CP_ASYNC16(dst, src, src_sz) \
    asm volatile("cp.async.cg.shared.global [%0], [%1], 16, %2;" \
                 :: "r"(dst), "l"(src), "r"(src_sz))
#define CP_COMMIT() asm volatile("cp.async.commit_group;" ::: "memory")
#define CP_WAIT1()  asm volatile("cp.async.wait_group 1;" ::: "memory")

// ---------------- CSR construction ----------------
#define CNT_BLOCKS 40
#define CNT_I4_PER_BLOCK (E_EDGES / 4 / CNT_BLOCKS)   // 4000

__global__ __launch_bounds__(256) void k_count(const int4* __restrict__ ei4) {
    __shared__ int h[N_NODES];
    const int tid = threadIdx.x;
    for (int i = tid; i < N_NODES; i += 256) h[i] = 0;
    __syncthreads();

    const int base = blockIdx.x * CNT_I4_PER_BLOCK;
    for (int i = base + tid; i < base + CNT_I4_PER_BLOCK; i += 256) {
        int4 r = ei4[i];
        atomicAdd(&h[min(max(r.x, 0), N_NODES - 1)], 1);
        atomicAdd(&h[min(max(r.y, 0), N_NODES - 1)], 1);
        atomicAdd(&h[min(max(r.z, 0), N_NODES - 1)], 1);
        atomicAdd(&h[min(max(r.w, 0), N_NODES - 1)], 1);
    }
    __syncthreads();

    for (int i = tid; i < N_NODES; i += 256) {
        int v = h[i];
        if (v) atomicAdd(&g_deg[i], v);
    }
}

// 1-block register-blocked scan: 1024 threads x 10 elements each (10240 >= N)
#define SCAN_PER 10
__global__ __launch_bounds__(1024) void k_scan() {
    const int tid  = threadIdx.x;
    const int lane = tid & 31;
    const int wid  = tid >> 5;
    const int base = tid * SCAN_PER;

    int excl_local[SCAN_PER];
    int sum = 0;
    #pragma unroll
    for (int q = 0; q < SCAN_PER; q++) {
        int i = base + q;
        int v = (i < N_NODES) ? g_deg[i] : 0;
        excl_local[q] = sum;
        sum += v;
    }

    int inc = sum;
    #pragma unroll
    for (int off = 1; off < 32; off <<= 1) {
        int t = __shfl_up_sync(0xFFFFFFFFu, inc, off);
        if (lane >= off) inc += t;
    }

    __shared__ int wsum[32];
    if (lane == 31) wsum[wid] = inc;
    __syncthreads();
    if (wid == 0) {
        int v = wsum[lane];
        int wi = v;
        #pragma unroll
        for (int off = 1; off < 32; off <<= 1) {
            int t = __shfl_up_sync(0xFFFFFFFFu, wi, off);
            if (lane >= off) wi += t;
        }
        wsum[lane] = wi - v;
    }
    __syncthreads();

    const int offset = wsum[wid] + (inc - sum);

    #pragma unroll
    for (int q = 0; q < SCAN_PER; q++) {
        int i = base + q;
        if (i < N_NODES) {
            int excl = offset + excl_local[q];
            g_rowptr[i] = excl;
            g_cursor[i] = excl;
            int d = g_deg[i];
            g_dinv[i] = (d > 0) ? rsqrtf((float)d) : 0.0f;
        }
    }
    if (tid == 1023) g_rowptr[N_NODES] = offset + sum;
}

__global__ void k_fill(const int4* __restrict__ ei4) {
    int i = blockIdx.x * blockDim.x + threadIdx.x;
    if (i < E_EDGES / 4) {
        int4 r = ei4[i];
        int4 c = ei4[E_EDGES / 4 + i];
        int rr[4] = {r.x, r.y, r.z, r.w};
        int cc[4] = {c.x, c.y, c.z, c.w};
        #pragma unroll
        for (int q = 0; q < 4; q++) {
            int rv = min(max(rr[q], 0), N_NODES - 1);
            int cv = min(max(cc[q], 0), N_NODES - 1);
            int pos = atomicAdd(&g_cursor[rv], 1);
            if (pos >= 0 && pos < E_EDGES) g_col[pos] = cv;
        }
    }
}

// ---------------- bf16 hi/lo split conversion ----------------
__global__ void k_cvt(const float4* __restrict__ src,
                      uint2* __restrict__ hi, uint2* __restrict__ lo, int n4) {
    int i = blockIdx.x * blockDim.x + threadIdx.x;
    if (i < n4) {
        float4 v = src[i];
        __nv_bfloat16 h[4], l[4];
        h[0] = __float2bfloat16_rn(v.x); l[0] = __float2bfloat16_rn(v.x - __bfloat162float(h[0]));
        h[1] = __float2bfloat16_rn(v.y); l[1] = __float2bfloat16_rn(v.y - __bfloat162float(h[1]));
        h[2] = __float2bfloat16_rn(v.z); l[2] = __float2bfloat16_rn(v.z - __bfloat162float(h[2]));
        h[3] = __float2bfloat16_rn(v.w); l[3] = __float2bfloat16_rn(v.w - __bfloat162float(h[3]));
        hi[i] = *reinterpret_cast<const uint2*>(h);
        lo[i] = *reinterpret_cast<const uint2*>(l);
    }
}

// ---------------- Tensor-core GEMM (bf16x3, mma.sync + ldmatrix + cp.async) ----------------
#define GBM 128
#define GBN 64
#define SMSTRIDE 24
#define STG_B    18432
#define OFF_AL   (128 * SMSTRIDE)
#define OFF_WH   (256 * SMSTRIDE)
#define OFF_WL   (320 * SMSTRIDE)
#define GEMM_SMEM (3 * STG_B)

__global__ __launch_bounds__(256) void k_gemm_mma(const float* __restrict__ bias,
                                                  float* __restrict__ out,
                                                  __half* __restrict__ mir) {
    extern __shared__ __nv_bfloat16 smem[];
    const uint32_t sbase = smem_u32(smem);

    const int tid  = threadIdx.x;
    const int wid  = tid >> 5;
    const int lane = tid & 31;
    const int bm   = blockIdx.x * GBM;
    const int bn   = blockIdx.y * GBN;
    const int wm   = (wid & 3) * 32;
    const int wn   = (wid >> 2) * 32;
    const int q    = lane >> 2;
    const int s    = lane & 3;

    const int lg   = lane >> 3;
    const int l8   = lane & 7;
    const int arow = l8 + ((lg & 1) << 3);
    const int acol = (lg >> 1) << 3;
    const int brow = l8 + ((lg >> 1) << 3);
    const int bcol = (lg & 1) << 3;

    const uint32_t aHiB = sbase + ((wm + arow) * SMSTRIDE + acol) * 2;
    const uint32_t aLoB = aHiB + OFF_AL * 2;
    const uint32_t bHiB = sbase + OFF_WH * 2 + ((wn + brow) * SMSTRIDE + bcol) * 2;
    const uint32_t bLoB = bHiB + (OFF_WL - OFF_WH) * 2;
    const int MI_B = 16 * SMSTRIDE * 2;

    const int ar = tid >> 1,  ak = (tid & 1) * 8;
    const int mv = (bm + ar < N_NODES) ? 16 : 0;
    const long ag = (long)min(bm + ar, N_NODES - 1) * IN_CH;
    const uint32_t dA = sbase + (ar * SMSTRIDE + ak) * 2;
    const int wr = tid >> 1,  wk = (tid & 1) * 8;
    const long wg = (long)(bn + wr) * IN_CH;
    const uint32_t dW = sbase + OFF_WH * 2 + (wr * SMSTRIDE + wk) * 2;

    #define ISSUE(ch, stg)                                                       \
    {                                                                            \
        const int k0_ = (ch) * 16;                                               \
        const uint32_t so_ = (stg) * STG_B;                                      \
        CP_ASYNC16(dA + so_,              &g_xh[ag + k0_ + ak], mv);             \
        CP_ASYNC16(dA + so_ + OFF_AL * 2, &g_xl[ag + k0_ + ak], mv);             \
        if (tid < 128) {                                                         \
            CP_ASYNC16(dW + so_,                          &g_wh[wg + k0_ + wk], 16); \
            CP_ASYNC16(dW + so_ + (OFF_WL - OFF_WH) * 2,  &g_wl[wg + k0_ + wk], 16); \
        }                                                                        \
        CP_COMMIT();                                                             \
    }

    float d[2][4][4];
    #pragma unroll
    for (int mi = 0; mi < 2; mi++)
        #pragma unroll
        for (int ni = 0; ni < 4; ni++)
            #pragma unroll
            for (int r = 0; r < 4; r++) d[mi][ni][r] = 0.0f;

    const int NCHUNK = IN_CH / 16;
    ISSUE(0, 0);
    ISSUE(1, 1);

    for (int ch = 0; ch < NCHUNK; ch++) {
        CP_WAIT1();
        __syncthreads();

        if (ch + 2 < NCHUNK) ISSUE(ch + 2, (ch + 2) % 3);

        const uint32_t so = (ch % 3) * STG_B;

        unsigned ah[2][4], al[2][4], bh[4][2], bl[4][2];
        #pragma unroll
        for (int mi = 0; mi < 2; mi++) {
            LDSM_X4(ah[mi][0], ah[mi][1], ah[mi][2], ah[mi][3], aHiB + so + mi * MI_B);
            LDSM_X4(al[mi][0], al[mi][1], al[mi][2], al[mi][3], aLoB + so + mi * MI_B);
        }
        #pragma unroll
        for (int p = 0; p < 2; p++) {
            unsigned t0, t1, t2, t3;
            LDSM_X4(t0, t1, t2, t3, bHiB + so + p * MI_B);
            bh[2 * p][0] = t0; bh[2 * p][1] = t1;
            bh[2 * p + 1][0] = t2; bh[2 * p + 1][1] = t3;
            LDSM_X4(t0, t1, t2, t3, bLoB + so + p * MI_B);
            bl[2 * p][0] = t0; bl[2 * p][1] = t1;
            bl[2 * p + 1][0] = t2; bl[2 * p + 1][1] = t3;
        }

        #pragma unroll
        for (int mi = 0; mi < 2; mi++) {
            #pragma unroll
            for (int ni = 0; ni < 4; ni++) MMA_BF16(d[mi][ni], ah[mi], bh[ni][0], bh[ni][1]);
            #pragma unroll
            for (int ni = 0; ni < 4; ni++) MMA_BF16(d[mi][ni], al[mi], bh[ni][0], bh[ni][1]);
            #pragma unroll
            for (int ni = 0; ni < 4; ni++) MMA_BF16(d[mi][ni], ah[mi], bl[ni][0], bl[ni][1]);
        }
    }
    #undef ISSUE

    float2 bv[4];
    #pragma unroll
    for (int ni = 0; ni < 4; ni++) {
        int c = bn + wn + ni * 8 + s * 2;
        bv[ni].x = bias[c];
        bv[ni].y = bias[c + 1];
    }

    #pragma unroll
    for (int mi = 0; mi < 2; mi++) {
        int r0 = bm + wm + mi * 16 + q;
        int r1 = r0 + 8;
        float di0 = (r0 < N_NODES) ? g_dinv[r0] : 0.0f;
        float di1 = (r1 < N_NODES) ? g_dinv[r1] : 0.0f;
        #pragma unroll
        for (int ni = 0; ni < 4; ni++) {
            int c = bn + wn + ni * 8 + s * 2;
            if (r0 < N_NODES) {
                float o0 = d[mi][ni][0] + bv[ni].x;
                float o1 = d[mi][ni][1] + bv[ni].y;
                *reinterpret_cast<float2*>(&out[(long)r0 * OUT_CH + c]) = make_float2(o0, o1);
                *reinterpret_cast<__half2*>(&mir[(long)r0 * OUT_CH + c]) =
                    __floats2half2_rn(o0 * di0, o1 * di0);
            }
            if (r1 < N_NODES) {
                float o0 = d[mi][ni][2] + bv[ni].x;
                float o1 = d[mi][ni][3] + bv[ni].y;
                *reinterpret_cast<float2*>(&out[(long)r1 * OUT_CH + c]) = make_float2(o0, o1);
                *reinterpret_cast<__half2*>(&mir[(long)r1 * OUT_CH + c]) =
                    __floats2half2_rn(o0 * di1, o1 * di1);
            }
        }
    }
}

// ---------------- int8 quantized row write (block = one row, 64 threads) --------
// v = value*dinv per channel (float4 per thread). Stores q (uint per thread) and
// per-row scale. Block-wide max via 2-warp shfl reduce + smem.
__device__ __forceinline__ void quantize_row_store(float4 v, int row, int tid,
                                                   unsigned* __restrict__ mq,
                                                   float* __restrict__ mscl) {
    float mx = fmaxf(fmaxf(fabsf(v.x), fabsf(v.y)), fmaxf(fabsf(v.z), fabsf(v.w)));
    #pragma unroll
    for (int off = 16; off > 0; off >>= 1)
        mx = fmaxf(mx, __shfl_xor_sync(0xFFFFFFFFu, mx, off));
    __shared__ float wmax[2];
    if ((tid & 31) == 0) wmax[tid >> 5] = mx;
    __syncthreads();
    mx = fmaxf(wmax[0], wmax[1]);
    float inv = (mx > 0.f) ? 127.0f / mx : 0.0f;
    int q0 = __float2int_rn(v.x * inv);
    int q1 = __float2int_rn(v.y * inv);
    int q2 = __float2int_rn(v.z * inv);
    int q3 = __float2int_rn(v.w * inv);
    unsigned packed = (unsigned)(q0 & 0xff) | ((unsigned)(q1 & 0xff) << 8) |
                      ((unsigned)(q2 & 0xff) << 16) | ((unsigned)(q3 & 0xff) << 24);
    mq[(long)row * 64 + tid] = packed;
    if (tid == 0) mscl[row] = (mx > 0.f) ? mx / 127.0f : 0.0f;
}

__device__ __forceinline__ float4 dec_i8(unsigned u) {
    return make_float4((float)((int)(u << 24) >> 24),
                       (float)((int)(u << 16) >> 24),
                       (float)((int)(u << 8)  >> 24),
                       (float)((int)u >> 24));
}

// ---------------- SpMM, fp16 input (hop 1): out=bufB, mirror=int8 q1/s1 ----------
__global__ __launch_bounds__(64) void k_spmm_f16(const uint2* __restrict__ h16,
                                                 const float4* __restrict__ base4,
                                                 const float* __restrict__ wptr,
                                                 float4* __restrict__ out4,
                                                 unsigned* __restrict__ mq,
                                                 float* __restrict__ mscl) {
    __shared__ int scol[256];

    const int row = blockIdx.x;
    const int tid = threadIdx.x;
    const int s   = g_rowptr[row];
    const int e   = g_rowptr[row + 1];

    float4 acc = make_float4(0.f, 0.f, 0.f, 0.f);

    for (int bs = s; bs < e; bs += 256) {
        int cnt = min(256, e - bs);
        for (int j = tid; j < cnt; j += 64) scol[j] = g_col[bs + j];
        __syncthreads();
        int j = 0;
        for (; j + 4 <= cnt; j += 4) {
            int c0 = scol[j + 0], c1 = scol[j + 1], c2 = scol[j + 2], c3 = scol[j + 3];
            uint2 u0 = h16[(long)c0 * 64 + tid];
            uint2 u1 = h16[(long)c1 * 64 + tid];
            uint2 u2 = h16[(long)c2 * 64 + tid];
            uint2 u3 = h16[(long)c3 * 64 + tid];
            float2 a0 = __half22float2(*reinterpret_cast<const __half2*>(&u0.x));
            float2 b0 = __half22float2(*reinterpret_cast<const __half2*>(&u0.y));
            float2 a1 = __half22float2(*reinterpret_cast<const __half2*>(&u1.x));
            float2 b1 = __half22float2(*reinterpret_cast<const __half2*>(&u1.y));
            float2 a2 = __half22float2(*reinterpret_cast<const __half2*>(&u2.x));
            float2 b2 = __half22float2(*reinterpret_cast<const __half2*>(&u2.y));
            float2 a3 = __half22float2(*reinterpret_cast<const __half2*>(&u3.x));
            float2 b3 = __half22float2(*reinterpret_cast<const __half2*>(&u3.y));
            acc.x += a0.x + a1.x + a2.x + a3.x;
            acc.y += a0.y + a1.y + a2.y + a3.y;
            acc.z += b0.x + b1.x + b2.x + b3.x;
            acc.w += b0.y + b1.y + b2.y + b3.y;
        }
        for (; j < cnt; j++) {
            uint2 u = h16[(long)scol[j] * 64 + tid];
            float2 a = __half22float2(*reinterpret_cast<const __half2*>(&u.x));
            float2 b = __half22float2(*reinterpret_cast<const __half2*>(&u.y));
            acc.x += a.x; acc.y += a.y; acc.z += b.x; acc.w += b.y;
        }
        __syncthreads();
    }

    const float di = g_dinv[row];
    const float wk = wptr[0];
    float4 bv = base4[(long)row * 64 + tid];
    float4 o;
    o.x = bv.x + wk * di * acc.x;
    o.y = bv.y + wk * di * acc.y;
    o.z = bv.z + wk * di * acc.z;
    o.w = bv.w + wk * di * acc.w;
    out4[(long)row * 64 + tid] = o;

    float4 v = make_float4(o.x * di, o.y * di, o.z * di, o.w * di);
    quantize_row_store(v, row, tid, mq, mscl);
}

// ---------------- SpMM, int8 input (hops 2/3) ----------
// acc = sum_e scale[c]*q[c]; r = dinv[row]*acc; o = base? base + w*r : r
// optional fp32 out; optional int8 mirror of o*dinv.
__global__ __launch_bounds__(64) void k_spmm_i8(const unsigned* __restrict__ hq,
                                                const float* __restrict__ hscl,
                                                const float4* __restrict__ base4,
                                                const float* __restrict__ wptr,
                                                int widx,
                                                float4* __restrict__ out4,
                                                unsigned* __restrict__ mq,
                                                float* __restrict__ mscl) {
    __shared__ int   scol[256];
    __shared__ float sscl[256];

    const int row = blockIdx.x;
    const int tid = threadIdx.x;
    const int s   = g_rowptr[row];
    const int e   = g_rowptr[row + 1];

    float4 acc = make_float4(0.f, 0.f, 0.f, 0.f);

    for (int bs = s; bs < e; bs += 256) {
        int cnt = min(256, e - bs);
        for (int j = tid; j < cnt; j += 64) {
            int c = g_col[bs + j];
            scol[j] = c;
            sscl[j] = hscl[c];
        }
        __syncthreads();
        int j = 0;
        for (; j + 4 <= cnt; j += 4) {
            int c0 = scol[j + 0], c1 = scol[j + 1], c2 = scol[j + 2], c3 = scol[j + 3];
            float s0 = sscl[j + 0], s1 = sscl[j + 1], s2 = sscl[j + 2], s3 = sscl[j + 3];
            unsigned u0 = hq[(long)c0 * 64 + tid];
            unsigned u1 = hq[(long)c1 * 64 + tid];
            unsigned u2 = hq[(long)c2 * 64 + tid];
            unsigned u3 = hq[(long)c3 * 64 + tid];
            float4 v0 = dec_i8(u0);
            float4 v1 = dec_i8(u1);
            float4 v2 = dec_i8(u2);
            float4 v3 = dec_i8(u3);
            acc.x += s0 * v0.x + s1 * v1.x + s2 * v2.x + s3 * v3.x;
            acc.y += s0 * v0.y + s1 * v1.y + s2 * v2.y + s3 * v3.y;
            acc.z += s0 * v0.z + s1 * v1.z + s2 * v2.z + s3 * v3.z;
            acc.w += s0 * v0.w + s1 * v1.w + s2 * v2.w + s3 * v3.w;
        }
        for (; j < cnt; j++) {
            float sc = sscl[j];
            float4 v = dec_i8(hq[(long)scol[j] * 64 + tid]);
            acc.x += sc * v.x; acc.y += sc * v.y; acc.z += sc * v.z; acc.w += sc * v.w;
        }
        __syncthreads();
    }

    const float di = g_dinv[row];
    float4 r;
    r.x = di * acc.x; r.y = di * acc.y; r.z = di * acc.z; r.w = di * acc.w;

    float4 o;
    if (base4 != nullptr) {
        float wk = wptr[widx];
        float4 bv = base4[(long)row * 64 + tid];
        o.x = bv.x + wk * r.x;
        o.y = bv.y + wk * r.y;
        o.z = bv.z + wk * r.z;
        o.w = bv.w + wk * r.w;
    } else {
        o = r;
    }
    if (out4 != nullptr) out4[(long)row * 64 + tid] = o;
    if (mq != nullptr) {
        float4 v = make_float4(o.x * di, o.y * di, o.z * di, o.w * di);
        quantize_row_store(v, row, tid, mq, mscl);
    }
}

// ---------------- launch ----------------
extern "C" void kernel_launch(void* const* d_in, const int* in_sizes, int n_in,
                              void* d_out, int out_size) {
    const float* x   = (const float*)d_in[0];
    const int*   ei  = (const int*)d_in[1];      // edge_index delivered as int32
    const float* lw  = (const float*)d_in[2];
    const float* lb  = (const float*)d_in[3];
    const float* wts = (const float*)d_in[4];
    float*       out = (float*)d_out;

    float* bufB;  __half* m0;
    unsigned *q1, *q2;  float *s1, *s2;
    __nv_bfloat16 *xh, *xl, *wh, *wl;
    int* degp;
    cudaGetSymbolAddress((void**)&bufB, g_bufB);
    cudaGetSymbolAddress((void**)&m0, g_m0);
    cudaGetSymbolAddress((void**)&q1, g_q1);
    cudaGetSymbolAddress((void**)&q2, g_q2);
    cudaGetSymbolAddress((void**)&s1, g_s1);
    cudaGetSymbolAddress((void**)&s2, g_s2);
    cudaGetSymbolAddress((void**)&xh, g_xh);
    cudaGetSymbolAddress((void**)&xl, g_xl);
    cudaGetSymbolAddress((void**)&wh, g_wh);
    cudaGetSymbolAddress((void**)&wl, g_wl);
    cudaGetSymbolAddress((void**)&degp, g_deg);

    // one-time infra (created on the non-capturing correctness call)
    static cudaStream_t s2s = nullptr;
    static cudaEvent_t evStart, evScan, evCvt, evFill;
    if (s2s == nullptr) {
        cudaStreamCreateWithFlags(&s2s, cudaStreamNonBlocking);
        cudaEventCreateWithFlags(&evStart, cudaEventDisableTiming);
        cudaEventCreateWithFlags(&evScan,  cudaEventDisableTiming);
        cudaEventCreateWithFlags(&evCvt,   cudaEventDisableTiming);
        cudaEventCreateWithFlags(&evFill,  cudaEventDisableTiming);
        cudaFuncSetAttribute(k_gemm_mma, cudaFuncAttributeMaxDynamicSharedMemorySize, GEMM_SMEM);
    }

    // fork side stream from the main (captured) stream
    cudaEventRecord(evStart, 0);
    cudaStreamWaitEvent(s2s, evStart, 0);

    // main stream: CSR degree + scan (produces dinv + cursor)
    cudaMemsetAsync(degp, 0, N_NODES * sizeof(int), 0);
    k_count<<<CNT_BLOCKS, 256>>>((const int4*)ei);
    k_scan<<<1, 1024>>>();
    cudaEventRecord(evScan, 0);

    // side stream: bf16 splits (independent), then fill (needs scan's cursor)
    {
        int n4 = (N_NODES * IN_CH) / 4;
        k_cvt<<<(n4 + 255) / 256, 256, 0, s2s>>>((const float4*)x, (uint2*)xh, (uint2*)xl, n4);
        int w4 = (OUT_CH * IN_CH) / 4;
        k_cvt<<<(w4 + 255) / 256, 256, 0, s2s>>>((const float4*)lw, (uint2*)wh, (uint2*)wl, w4);
    }
    cudaEventRecord(evCvt, s2s);
    cudaStreamWaitEvent(s2s, evScan, 0);
    k_fill<<<(E_EDGES / 4 + 255) / 256, 256, 0, s2s>>>((const int4*)ei);
    cudaEventRecord(evFill, s2s);

    // main stream: GEMM (needs cvt + scan); fill overlaps with it on s2s
    cudaStreamWaitEvent(0, evCvt, 0);
    dim3 ggrid((N_NODES + GBM - 1) / GBM, OUT_CH / GBN);
    k_gemm_mma<<<ggrid, 256, GEMM_SMEM>>>(lb, out, m0);

    // join fill before SpMM chain
    cudaStreamWaitEvent(0, evFill, 0);

    // k=0: bufB = out0 + w0 * A(out0); mirror q1/s1 = int8(bufB * dinv)
    k_spmm_f16<<<N_NODES, 64>>>((const uint2*)m0, (const float4*)out, wts,
                                (float4*)bufB, q1, s1);
    // k=1 hop 1: q2/s2 = int8(A(bufB) * dinv)   (fp32 output not needed)
    k_spmm_i8<<<N_NODES, 64>>>(q1, s1, nullptr, wts, 0, nullptr, q2, s2);
    // k=1 hop 2: d_out = bufB + w1 * A(prev)
    k_spmm_i8<<<N_NODES, 64>>>(q2, s2, (const float4*)bufB, wts, 1,
                               (float4*)out, nullptr, nullptr);
}

// round 15
// speedup vs baseline: 1.1006x; 1.1006x over previous
#include <cuda_runtime.h>
#include <cuda_fp16.h>
#include <cuda_bf16.h>
#include <cstdint>

#define N_NODES 10000
#define E_EDGES 640000
#define IN_CH   512
#define OUT_CH  256

// ---------------- device-global scratch (no allocations allowed) ----------------
__device__ int    g_deg[N_NODES];
__device__ int    g_rowptr[N_NODES + 1];
__device__ int    g_cursor[N_NODES];
__device__ float  g_dinv[N_NODES];
__device__ int    g_col[E_EDGES];
__device__ float  g_bufB[N_NODES * OUT_CH];
// fp16 gather mirrors (pre-scaled by dinv[row])
__device__ __half g_m0[N_NODES * OUT_CH];
__device__ __half g_m1[N_NODES * OUT_CH];
__device__ __half g_m2[N_NODES * OUT_CH];
// bf16 hi/lo splits for the tensor-core GEMM
__device__ __nv_bfloat16 g_xh[N_NODES * IN_CH];
__device__ __nv_bfloat16 g_xl[N_NODES * IN_CH];
__device__ __nv_bfloat16 g_wh[OUT_CH * IN_CH];
__device__ __nv_bfloat16 g_wl[OUT_CH * IN_CH];

__device__ __forceinline__ uint32_t smem_u32(const void* p) {
    uint32_t a;
    asm("{ .reg .u64 t; cvta.to.shared.u64 t, %1; cvt.u32.u64 %0, t; }" : "=r"(a) : "l"(p));
    return a;
}

#define LDSM_X4(r0, r1, r2, r3, addr) \
    asm volatile("ldmatrix.sync.aligned.m8n8.x4.shared.b16 {%0,%1,%2,%3}, [%4];" \
                 : "=r"(r0), "=r"(r1), "=r"(r2), "=r"(r3) : "r"(addr))

#define MMA_BF16(d, a, b0, b1) \
    asm volatile( \
        "mma.sync.aligned.m16n8k16.row.col.f32.bf16.bf16.f32 " \
        "{%0,%1,%2,%3}, {%4,%5,%6,%7}, {%8,%9}, {%0,%1,%2,%3};" \
        : "+f"((d)[0]), "+f"((d)[1]), "+f"((d)[2]), "+f"((d)[3]) \
        : "r"((a)[0]), "r"((a)[1]), "r"((a)[2]), "r"((a)[3]), "r"(b0), "r"(b1))

// 16B async copy; src_sz = 16 (copy) or 0 (zero-fill)
#define CP_ASYNC16(dst, src, src_sz) \
    asm volatile("cp.async.cg.shared.global [%0], [%1], 16, %2;" \
                 :: "r"(dst), "l"(src), "r"(src_sz))
#define CP_COMMIT() asm volatile("cp.async.commit_group;" ::: "memory")
#define CP_WAIT1()  asm volatile("cp.async.wait_group 1;" ::: "memory")

// ---------------- CSR construction ----------------
#define CNT_BLOCKS 40
#define CNT_I4_PER_BLOCK (E_EDGES / 4 / CNT_BLOCKS)   // 4000

__global__ __launch_bounds__(256) void k_count(const int4* __restrict__ ei4) {
    __shared__ int h[N_NODES];
    const int tid = threadIdx.x;
    for (int i = tid; i < N_NODES; i += 256) h[i] = 0;
    __syncthreads();

    const int base = blockIdx.x * CNT_I4_PER_BLOCK;
    for (int i = base + tid; i < base + CNT_I4_PER_BLOCK; i += 256) {
        int4 r = ei4[i];
        atomicAdd(&h[min(max(r.x, 0), N_NODES - 1)], 1);
        atomicAdd(&h[min(max(r.y, 0), N_NODES - 1)], 1);
        atomicAdd(&h[min(max(r.z, 0), N_NODES - 1)], 1);
        atomicAdd(&h[min(max(r.w, 0), N_NODES - 1)], 1);
    }
    __syncthreads();

    for (int i = tid; i < N_NODES; i += 256) {
        int v = h[i];
        if (v) atomicAdd(&g_deg[i], v);
    }
}

// 1-block register-blocked scan: 1024 threads x 10 elements each (10240 >= N)
#define SCAN_PER 10
__global__ __launch_bounds__(1024) void k_scan() {
    const int tid  = threadIdx.x;
    const int lane = tid & 31;
    const int wid  = tid >> 5;
    const int base = tid * SCAN_PER;

    int excl_local[SCAN_PER];
    int sum = 0;
    #pragma unroll
    for (int q = 0; q < SCAN_PER; q++) {
        int i = base + q;
        int v = (i < N_NODES) ? g_deg[i] : 0;
        excl_local[q] = sum;
        sum += v;
    }

    int inc = sum;
    #pragma unroll
    for (int off = 1; off < 32; off <<= 1) {
        int t = __shfl_up_sync(0xFFFFFFFFu, inc, off);
        if (lane >= off) inc += t;
    }

    __shared__ int wsum[32];
    if (lane == 31) wsum[wid] = inc;
    __syncthreads();
    if (wid == 0) {
        int v = wsum[lane];
        int wi = v;
        #pragma unroll
        for (int off = 1; off < 32; off <<= 1) {
            int t = __shfl_up_sync(0xFFFFFFFFu, wi, off);
            if (lane >= off) wi += t;
        }
        wsum[lane] = wi - v;
    }
    __syncthreads();

    const int offset = wsum[wid] + (inc - sum);

    #pragma unroll
    for (int q = 0; q < SCAN_PER; q++) {
        int i = base + q;
        if (i < N_NODES) {
            int excl = offset + excl_local[q];
            g_rowptr[i] = excl;
            g_cursor[i] = excl;
            int d = g_deg[i];
            g_dinv[i] = (d > 0) ? rsqrtf((float)d) : 0.0f;
        }
    }
    if (tid == 1023) g_rowptr[N_NODES] = offset + sum;
}

__global__ void k_fill(const int4* __restrict__ ei4) {
    int i = blockIdx.x * blockDim.x + threadIdx.x;
    if (i < E_EDGES / 4) {
        int4 r = ei4[i];
        int4 c = ei4[E_EDGES / 4 + i];
        int rr[4] = {r.x, r.y, r.z, r.w};
        int cc[4] = {c.x, c.y, c.z, c.w};
        #pragma unroll
        for (int q = 0; q < 4; q++) {
            int rv = min(max(rr[q], 0), N_NODES - 1);
            int cv = min(max(cc[q], 0), N_NODES - 1);
            int pos = atomicAdd(&g_cursor[rv], 1);
            if (pos >= 0 && pos < E_EDGES) g_col[pos] = cv;
        }
    }
}

// ---------------- bf16 hi/lo split conversion ----------------
__global__ void k_cvt(const float4* __restrict__ src,
                      uint2* __restrict__ hi, uint2* __restrict__ lo, int n4) {
    int i = blockIdx.x * blockDim.x + threadIdx.x;
    if (i < n4) {
        float4 v = src[i];
        __nv_bfloat16 h[4], l[4];
        h[0] = __float2bfloat16_rn(v.x); l[0] = __float2bfloat16_rn(v.x - __bfloat162float(h[0]));
        h[1] = __float2bfloat16_rn(v.y); l[1] = __float2bfloat16_rn(v.y - __bfloat162float(h[1]));
        h[2] = __float2bfloat16_rn(v.z); l[2] = __float2bfloat16_rn(v.z - __bfloat162float(h[2]));
        h[3] = __float2bfloat16_rn(v.w); l[3] = __float2bfloat16_rn(v.w - __bfloat162float(h[3]));
        hi[i] = *reinterpret_cast<const uint2*>(h);
        lo[i] = *reinterpret_cast<const uint2*>(l);
    }
}

// ---------------- Tensor-core GEMM (bf16x3, mma.sync + ldmatrix + cp.async) ----------------
// out[n,o] = sum_k x[n,k]*W[o,k] + b[o]; also mir = fp16(out*dinv[n]).
// CTA tile 128x128, 8 warps (warp tile 32x64), 3-stage cp.async pipeline, k16 chunks.
// 3 segment MMAs per chunk: Ah*Wh + Al*Wh + Ah*Wl (bl loaded after bh retires).
#define GBM 128
#define GBN 128
#define SMSTRIDE 24                       // bf16 per smem row (16 data + 8 pad)
#define STG_B    24576                    // (128A hi + 128A lo + 128W hi + 128W lo)*24*2
#define OFF_AL   (128 * SMSTRIDE)
#define OFF_WH   (256 * SMSTRIDE)
#define OFF_WL   (384 * SMSTRIDE)
#define GEMM_SMEM (3 * STG_B)             // 73728 bytes

__global__ __launch_bounds__(256, 2) void k_gemm_mma(const float* __restrict__ bias,
                                                     float* __restrict__ out,
                                                     __half* __restrict__ mir) {
    extern __shared__ __nv_bfloat16 smem[];
    const uint32_t sbase = smem_u32(smem);

    const int tid  = threadIdx.x;
    const int wid  = tid >> 5;          // 0..7
    const int lane = tid & 31;
    const int bm   = blockIdx.x * GBM;
    const int bn   = blockIdx.y * GBN;
    const int wm   = (wid & 3) * 32;    // 0,32,64,96
    const int wn   = (wid >> 2) * 64;   // 0,64
    const int q    = lane >> 2;
    const int s    = lane & 3;

    // ldmatrix lane geometry
    const int lg   = lane >> 3;
    const int l8   = lane & 7;
    const int arow = l8 + ((lg & 1) << 3);
    const int acol = (lg >> 1) << 3;
    const int brow = l8 + ((lg >> 1) << 3);
    const int bcol = (lg & 1) << 3;

    const uint32_t aHiB = sbase + ((wm + arow) * SMSTRIDE + acol) * 2;
    const uint32_t aLoB = aHiB + OFF_AL * 2;
    const uint32_t bHiB = sbase + OFF_WH * 2 + ((wn + brow) * SMSTRIDE + bcol) * 2;
    const uint32_t bLoB = sbase + OFF_WL * 2 + ((wn + brow) * SMSTRIDE + bcol) * 2;
    const int MI_B = 16 * SMSTRIDE * 2;   // 768 bytes per 16-row step

    // cp.async loader geometry: A and W each 128 rows x 2 halves = 256 x 16B chunks;
    // every thread does exactly one 16B chunk per matrix (hi+lo) => 4 per thread.
    const int ar = tid >> 1,  ak = (tid & 1) * 8;
    const int mv = (bm + ar < N_NODES) ? 16 : 0;
    const long ag = (long)min(bm + ar, N_NODES - 1) * IN_CH;
    const uint32_t dA = sbase + (ar * SMSTRIDE + ak) * 2;
    const long wg = (long)(bn + ar) * IN_CH;
    const uint32_t dW = sbase + OFF_WH * 2 + (ar * SMSTRIDE + ak) * 2;

    #define ISSUE(ch, stg)                                                       \
    {                                                                            \
        const int k0_ = (ch) * 16;                                               \
        const uint32_t so_ = (stg) * STG_B;                                      \
        CP_ASYNC16(dA + so_,                         &g_xh[ag + k0_ + ak], mv);  \
        CP_ASYNC16(dA + so_ + OFF_AL * 2,            &g_xl[ag + k0_ + ak], mv);  \
        CP_ASYNC16(dW + so_,                         &g_wh[wg + k0_ + ak], 16);  \
        CP_ASYNC16(dW + so_ + (OFF_WL - OFF_WH) * 2, &g_wl[wg + k0_ + ak], 16);  \
        CP_COMMIT();                                                             \
    }

    float d[2][8][4];
    #pragma unroll
    for (int mi = 0; mi < 2; mi++)
        #pragma unroll
        for (int ni = 0; ni < 8; ni++)
            #pragma unroll
            for (int r = 0; r < 4; r++) d[mi][ni][r] = 0.0f;

    const int NCHUNK = IN_CH / 16;   // 32
    ISSUE(0, 0);
    ISSUE(1, 1);

    for (int ch = 0; ch < NCHUNK; ch++) {
        CP_WAIT1();
        __syncthreads();   // stage ch%3 ready everywhere; all warps past compute(ch-1)

        if (ch + 2 < NCHUNK) ISSUE(ch + 2, (ch + 2) % 3);

        const uint32_t so = (ch % 3) * STG_B;

        // A fragments (hi+lo) and B-hi fragments
        unsigned ah[2][4], al[2][4], bfr[8][2];
        #pragma unroll
        for (int mi = 0; mi < 2; mi++) {
            LDSM_X4(ah[mi][0], ah[mi][1], ah[mi][2], ah[mi][3], aHiB + so + mi * MI_B);
            LDSM_X4(al[mi][0], al[mi][1], al[mi][2], al[mi][3], aLoB + so + mi * MI_B);
        }
        #pragma unroll
        for (int p = 0; p < 4; p++) {
            unsigned t0, t1, t2, t3;
            LDSM_X4(t0, t1, t2, t3, bHiB + so + p * MI_B);
            bfr[2 * p][0] = t0; bfr[2 * p][1] = t1;
            bfr[2 * p + 1][0] = t2; bfr[2 * p + 1][1] = t3;
        }

        // segments 1+2 use bh
        #pragma unroll
        for (int mi = 0; mi < 2; mi++) {
            #pragma unroll
            for (int ni = 0; ni < 8; ni++) MMA_BF16(d[mi][ni], ah[mi], bfr[ni][0], bfr[ni][1]);
            #pragma unroll
            for (int ni = 0; ni < 8; ni++) MMA_BF16(d[mi][ni], al[mi], bfr[ni][0], bfr[ni][1]);
        }
        // load B-lo over retired bh registers, then segment 3
        #pragma unroll
        for (int p = 0; p < 4; p++) {
            unsigned t0, t1, t2, t3;
            LDSM_X4(t0, t1, t2, t3, bLoB + so + p * MI_B);
            bfr[2 * p][0] = t0; bfr[2 * p][1] = t1;
            bfr[2 * p + 1][0] = t2; bfr[2 * p + 1][1] = t3;
        }
        #pragma unroll
        for (int mi = 0; mi < 2; mi++) {
            #pragma unroll
            for (int ni = 0; ni < 8; ni++) MMA_BF16(d[mi][ni], ah[mi], bfr[ni][0], bfr[ni][1]);
        }
    }
    #undef ISSUE

    // ---- epilogue: bias, fp32 out, fp16 mirror (scaled by dinv) ----
    float2 bv[8];
    #pragma unroll
    for (int ni = 0; ni < 8; ni++) {
        int c = bn + wn + ni * 8 + s * 2;
        bv[ni].x = bias[c];
        bv[ni].y = bias[c + 1];
    }

    #pragma unroll
    for (int mi = 0; mi < 2; mi++) {
        int r0 = bm + wm + mi * 16 + q;
        int r1 = r0 + 8;
        float di0 = (r0 < N_NODES) ? g_dinv[r0] : 0.0f;
        float di1 = (r1 < N_NODES) ? g_dinv[r1] : 0.0f;
        #pragma unroll
        for (int ni = 0; ni < 8; ni++) {
            int c = bn + wn + ni * 8 + s * 2;
            if (r0 < N_NODES) {
                float o0 = d[mi][ni][0] + bv[ni].x;
                float o1 = d[mi][ni][1] + bv[ni].y;
                *reinterpret_cast<float2*>(&out[(long)r0 * OUT_CH + c]) = make_float2(o0, o1);
                *reinterpret_cast<__half2*>(&mir[(long)r0 * OUT_CH + c]) =
                    __floats2half2_rn(o0 * di0, o1 * di0);
            }
            if (r1 < N_NODES) {
                float o0 = d[mi][ni][2] + bv[ni].x;
                float o1 = d[mi][ni][3] + bv[ni].y;
                *reinterpret_cast<float2*>(&out[(long)r1 * OUT_CH + c]) = make_float2(o0, o1);
                *reinterpret_cast<__half2*>(&mir[(long)r1 * OUT_CH + c]) =
                    __floats2half2_rn(o0 * di1, o1 * di1);
            }
        }
    }
}

// ---------------- SpMM gather: one row per 64-thread block ----------------
__global__ __launch_bounds__(64) void k_spmm(const uint2* __restrict__ h16,
                                             const float4* __restrict__ base4,
                                             const float* __restrict__ wptr,
                                             int widx,
                                             float4* __restrict__ out4,
                                             uint2* __restrict__ mir) {
    __shared__ int scol[256];

    const int row = blockIdx.x;
    const int tid = threadIdx.x;        // 0..63, owns 4 channels
    const int s   = g_rowptr[row];
    const int e   = g_rowptr[row + 1];

    float4 acc = make_float4(0.f, 0.f, 0.f, 0.f);

    for (int bs = s; bs < e; bs += 256) {
        int cnt = min(256, e - bs);
        for (int j = tid; j < cnt; j += 64) scol[j] = g_col[bs + j];
        __syncthreads();
        int j = 0;
        for (; j + 4 <= cnt; j += 4) {
            int c0 = scol[j + 0], c1 = scol[j + 1], c2 = scol[j + 2], c3 = scol[j + 3];
            uint2 u0 = h16[(long)c0 * 64 + tid];
            uint2 u1 = h16[(long)c1 * 64 + tid];
            uint2 u2 = h16[(long)c2 * 64 + tid];
            uint2 u3 = h16[(long)c3 * 64 + tid];
            float2 a0 = __half22float2(*reinterpret_cast<const __half2*>(&u0.x));
            float2 b0 = __half22float2(*reinterpret_cast<const __half2*>(&u0.y));
            float2 a1 = __half22float2(*reinterpret_cast<const __half2*>(&u1.x));
            float2 b1 = __half22float2(*reinterpret_cast<const __half2*>(&u1.y));
            float2 a2 = __half22float2(*reinterpret_cast<const __half2*>(&u2.x));
            float2 b2 = __half22float2(*reinterpret_cast<const __half2*>(&u2.y));
            float2 a3 = __half22float2(*reinterpret_cast<const __half2*>(&u3.x));
            float2 b3 = __half22float2(*reinterpret_cast<const __half2*>(&u3.y));
            acc.x += a0.x + a1.x + a2.x + a3.x;
            acc.y += a0.y + a1.y + a2.y + a3.y;
            acc.z += b0.x + b1.x + b2.x + b3.x;
            acc.w += b0.y + b1.y + b2.y + b3.y;
        }
        for (; j < cnt; j++) {
            uint2 u = h16[(long)scol[j] * 64 + tid];
            float2 a = __half22float2(*reinterpret_cast<const __half2*>(&u.x));
            float2 b = __half22float2(*reinterpret_cast<const __half2*>(&u.y));
            acc.x += a.x; acc.y += a.y; acc.z += b.x; acc.w += b.y;
        }
        __syncthreads();
    }

    const float di = g_dinv[row];
    float4 r;
    r.x = di * acc.x; r.y = di * acc.y; r.z = di * acc.z; r.w = di * acc.w;

    float4 o;
    if (base4 != nullptr) {
        float wk = wptr[widx];
        float4 bv = base4[(long)row * 64 + tid];
        o.x = bv.x + wk * r.x;
        o.y = bv.y + wk * r.y;
        o.z = bv.z + wk * r.z;
        o.w = bv.w + wk * r.w;
    } else {
        o = r;
    }
    if (out4 != nullptr) out4[(long)row * 64 + tid] = o;
    if (mir != nullptr) {
        __half h[4];
        h[0] = __float2half(o.x * di);
        h[1] = __float2half(o.y * di);
        h[2] = __float2half(o.z * di);
        h[3] = __float2half(o.w * di);
        mir[(long)row * 64 + tid] = *reinterpret_cast<const uint2*>(h);
    }
}

// ---------------- launch ----------------
extern "C" void kernel_launch(void* const* d_in, const int* in_sizes, int n_in,
                              void* d_out, int out_size) {
    const float* x   = (const float*)d_in[0];
    const int*   ei  = (const int*)d_in[1];      // edge_index delivered as int32
    const float* lw  = (const float*)d_in[2];
    const float* lb  = (const float*)d_in[3];
    const float* wts = (const float*)d_in[4];
    float*       out = (float*)d_out;

    float* bufB;  __half *m0, *m1, *m2;
    __nv_bfloat16 *xh, *xl, *wh, *wl;
    int* degp;
    cudaGetSymbolAddress((void**)&bufB, g_bufB);
    cudaGetSymbolAddress((void**)&m0, g_m0);
    cudaGetSymbolAddress((void**)&m1, g_m1);
    cudaGetSymbolAddress((void**)&m2, g_m2);
    cudaGetSymbolAddress((void**)&xh, g_xh);
    cudaGetSymbolAddress((void**)&xl, g_xl);
    cudaGetSymbolAddress((void**)&wh, g_wh);
    cudaGetSymbolAddress((void**)&wl, g_wl);
    cudaGetSymbolAddress((void**)&degp, g_deg);

    // one-time infra (created on the non-capturing correctness call)
    static cudaStream_t s2 = nullptr;
    static cudaEvent_t evStart, evScan, evCvt, evFill;
    if (s2 == nullptr) {
        cudaStreamCreateWithFlags(&s2, cudaStreamNonBlocking);
        cudaEventCreateWithFlags(&evStart, cudaEventDisableTiming);
        cudaEventCreateWithFlags(&evScan,  cudaEventDisableTiming);
        cudaEventCreateWithFlags(&evCvt,   cudaEventDisableTiming);
        cudaEventCreateWithFlags(&evFill,  cudaEventDisableTiming);
        cudaFuncSetAttribute(k_gemm_mma, cudaFuncAttributeMaxDynamicSharedMemorySize, GEMM_SMEM);
    }

    // fork side stream from the main (captured) stream
    cudaEventRecord(evStart, 0);
    cudaStreamWaitEvent(s2, evStart, 0);

    // main stream: CSR degree + scan (produces dinv + cursor)
    cudaMemsetAsync(degp, 0, N_NODES * sizeof(int), 0);
    k_count<<<CNT_BLOCKS, 256>>>((const int4*)ei);
    k_scan<<<1, 1024>>>();
    cudaEventRecord(evScan, 0);

    // side stream: bf16 splits (independent), then fill (needs scan's cursor)
    {
        int n4 = (N_NODES * IN_CH) / 4;
        k_cvt<<<(n4 + 255) / 256, 256, 0, s2>>>((const float4*)x, (uint2*)xh, (uint2*)xl, n4);
        int w4 = (OUT_CH * IN_CH) / 4;
        k_cvt<<<(w4 + 255) / 256, 256, 0, s2>>>((const float4*)lw, (uint2*)wh, (uint2*)wl, w4);
    }
    cudaEventRecord(evCvt, s2);
    cudaStreamWaitEvent(s2, evScan, 0);
    k_fill<<<(E_EDGES / 4 + 255) / 256, 256, 0, s2>>>((const int4*)ei);
    cudaEventRecord(evFill, s2);

    // main stream: GEMM (needs cvt + scan); fill overlaps with it on s2
    cudaStreamWaitEvent(0, evCvt, 0);
    dim3 ggrid((N_NODES + GBM - 1) / GBM, OUT_CH / GBN);
    k_gemm_mma<<<ggrid, 256, GEMM_SMEM>>>(lb, out, m0);

    // join fill before SpMM chain
    cudaStreamWaitEvent(0, evFill, 0);

    // k=0: bufB = out0 + w0 * A(out0); m1 = fp16(bufB * dinv)
    k_spmm<<<N_NODES, 64>>>((const uint2*)m0, (const float4*)out, wts, 0,
                            (float4*)bufB, (uint2*)m1);
    // k=1 hop 1: m2 = fp16(A(bufB) * dinv)   (fp32 output not needed)
    k_spmm<<<N_NODES, 64>>>((const uint2*)m1, nullptr, wts, 0,
                            nullptr, (uint2*)m2);
    // k=1 hop 2: d_out = bufB + w1 * A(prev)
    k_spmm<<<N_NODES, 64>>>((const uint2*)m2, (const float4*)bufB, wts, 1,
                            (float4*)out, nullptr);
}